// round 11
// baseline (speedup 1.0000x reference)
#include <cuda_runtime.h>
#include <cuda_bf16.h>
#include <cstdint>

#define Bx   16
#define Nn   1024
#define DINc 128
#define Hh   4
#define Dd   32
#define HD   128
#define BN   (Bx*Nn)
#define LOG2E 1.4426950408889634f

// ---------------------------------------------------------------------------
// Scratch (device globals — no allocation allowed in kernel_launch)
// ---------------------------------------------------------------------------
__device__ float    g_hT[(size_t)Bx*Hh*Nn*Dd];   // 8.4 MB tf32-rounded, [b][hh][j][d]
__device__ float    g_Ei[(size_t)Hh*BN];         // exp2(ei)      [hh][row]
__device__ float    g_Fi[(size_t)Hh*BN];         // exp2(0.2 ei)
__device__ float    g_Ej[(size_t)Hh*BN];
__device__ float    g_Fj[(size_t)Hh*BN];
__device__ unsigned g_am[(size_t)32*BN];         // [jt][row] packed adjacency bits
__device__ float    g_pnum[(size_t)2*Bx*Hh*Nn*32]; // 16.8 MB partial numerators
__device__ float    g_pden[(size_t)2*Bx*Hh*Nn];    // partial denominators

__device__ __forceinline__ float tf32r(float x) {
    uint32_t u; asm("cvt.rna.tf32.f32 %0, %1;" : "=r"(u) : "f"(x));
    return __uint_as_float(u);
}
__device__ __forceinline__ float ex2(float x) {
    float p; asm("ex2.approx.ftz.f32 %0, %1;" : "=f"(p) : "f"(x));
    return p;
}

#define MMA_TF32(c0,c1,c2,c3, A0,A1,A2,A3, B0,B1) \
    asm("mma.sync.aligned.m16n8k8.row.col.f32.tf32.tf32.f32 " \
        "{%0,%1,%2,%3}, {%4,%5,%6,%7}, {%8,%9}, {%0,%1,%2,%3};" \
        : "+f"(c0), "+f"(c1), "+f"(c2), "+f"(c3) \
        : "r"(A0), "r"(A1), "r"(A2), "r"(A3), "r"(B0), "r"(B1))

// ---------------------------------------------------------------------------
// Kernel 1 (fused): h = x@W + b via 3xTF32 mma.sync  ->  g_hT,
// edge logits from accumulator fragments -> g_Ei/Fi/Ej/Fj,
// adjacency bit-packing -> g_am.   (identical to R10)
// ---------------------------------------------------------------------------
__global__ void __launch_bounds__(256, 2) k_gemm(const float* __restrict__ x,
                                                 const float* __restrict__ W,
                                                 const float* __restrict__ bias,
                                                 const float* __restrict__ a,
                                                 const int* __restrict__ adj) {
    __shared__ __align__(16) float xs[32*132];
    __shared__ float as[64];
    const int tid  = threadIdx.x;
    const int lane = tid & 31;
    const int w    = tid >> 5;
    const int qid  = lane >> 2;
    const int tq   = lane & 3;
    const int m0   = (w & 1) * 16;
    const int hh   = w >> 1;
    const int n0   = hh * 32;
    const size_t row0 = (size_t)blockIdx.x * 32;

    for (int i = tid; i < 32*32; i += 256) {
        const int r = i >> 5, c4 = i & 31;
        float4 v = ((const float4*)(x + (row0 + r)*DINc))[c4];
        *(float4*)&xs[r*132 + c4*4] = v;
    }
    if (tid < 64) as[tid] = a[tid];
    __syncthreads();

    float acc[4][4];
#pragma unroll
    for (int nt = 0; nt < 4; nt++)
#pragma unroll
        for (int k = 0; k < 4; k++) acc[nt][k] = 0.f;

#pragma unroll
    for (int ks = 0; ks < 16; ks++) {
        const int k0 = ks*8;
        float wv0[4], wv1[4];
        const float* Wk = W + (size_t)(k0 + tq)*HD + n0 + qid;
#pragma unroll
        for (int nt = 0; nt < 4; nt++) wv0[nt] = __ldg(Wk + nt*8);
#pragma unroll
        for (int nt = 0; nt < 4; nt++) wv1[nt] = __ldg(Wk + 4*HD + nt*8);

        const float av0 = xs[(m0+qid  )*132 + k0 + tq];
        const float av1 = xs[(m0+qid+8)*132 + k0 + tq];
        const float av2 = xs[(m0+qid  )*132 + k0 + tq + 4];
        const float av3 = xs[(m0+qid+8)*132 + k0 + tq + 4];
        const float ah0 = tf32r(av0), ah1 = tf32r(av1), ah2 = tf32r(av2), ah3 = tf32r(av3);
        const uint32_t Ah0 = __float_as_uint(ah0), Ah1 = __float_as_uint(ah1);
        const uint32_t Ah2 = __float_as_uint(ah2), Ah3 = __float_as_uint(ah3);
        const uint32_t Al0 = __float_as_uint(av0 - ah0), Al1 = __float_as_uint(av1 - ah1);
        const uint32_t Al2 = __float_as_uint(av2 - ah2), Al3 = __float_as_uint(av3 - ah3);

#pragma unroll
        for (int nt = 0; nt < 4; nt++) {
            const float bh0 = tf32r(wv0[nt]), bh1 = tf32r(wv1[nt]);
            const uint32_t Bh0 = __float_as_uint(bh0), Bh1 = __float_as_uint(bh1);
            const uint32_t Bl0 = __float_as_uint(wv0[nt] - bh0);
            const uint32_t Bl1 = __float_as_uint(wv1[nt] - bh1);
            MMA_TF32(acc[nt][0], acc[nt][1], acc[nt][2], acc[nt][3],
                     Ah0, Ah1, Ah2, Ah3, Bl0, Bl1);
            MMA_TF32(acc[nt][0], acc[nt][1], acc[nt][2], acc[nt][3],
                     Al0, Al1, Al2, Al3, Bh0, Bh1);
            MMA_TF32(acc[nt][0], acc[nt][1], acc[nt][2], acc[nt][3],
                     Ah0, Ah1, Ah2, Ah3, Bh0, Bh1);
        }
    }

    const int b  = (int)(row0 >> 10);
    const int jt = (int)((row0 >> 5) & 31);
    float* htb = g_hT + (((size_t)b*Hh + hh) << 15) + ((size_t)jt*32 << 5);

    float si0 = 0.f, si1 = 0.f, sj0 = 0.f, sj1 = 0.f;
#pragma unroll
    for (int nt = 0; nt < 4; nt++) {
        const int d0 = nt*8 + 2*tq;
        const float bc0 = __ldg(&bias[n0 + d0]), bc1 = __ldg(&bias[n0 + d0 + 1]);
        const float h00 = acc[nt][0] + bc0, h01 = acc[nt][1] + bc1;
        const float h10 = acc[nt][2] + bc0, h11 = acc[nt][3] + bc1;
        const float ai0 = as[d0], ai1 = as[d0 + 1];
        const float aj0 = as[32 + d0], aj1 = as[32 + d0 + 1];
        si0 = fmaf(h00, ai0, fmaf(h01, ai1, si0));
        si1 = fmaf(h10, ai0, fmaf(h11, ai1, si1));
        sj0 = fmaf(h00, aj0, fmaf(h01, aj1, sj0));
        sj1 = fmaf(h10, aj0, fmaf(h11, aj1, sj1));
        float2 v0 = { tf32r(h00), tf32r(h01) };
        float2 v1 = { tf32r(h10), tf32r(h11) };
        *(float2*)(htb + (size_t)(m0 + qid    )*32 + d0) = v0;
        *(float2*)(htb + (size_t)(m0 + qid + 8)*32 + d0) = v1;
    }
#pragma unroll
    for (int o = 1; o <= 2; o <<= 1) {
        si0 += __shfl_xor_sync(0xffffffffu, si0, o);
        si1 += __shfl_xor_sync(0xffffffffu, si1, o);
        sj0 += __shfl_xor_sync(0xffffffffu, sj0, o);
        sj1 += __shfl_xor_sync(0xffffffffu, sj1, o);
    }
    if (tq == 0) {
        const size_t r0g = (size_t)hh*BN + row0 + m0 + qid;
        const float e0 = si0*LOG2E, e1 = si1*LOG2E;
        const float f0 = sj0*LOG2E, f1 = sj1*LOG2E;
        g_Ei[r0g]     = ex2(e0);      g_Ei[r0g + 8] = ex2(e1);
        g_Fi[r0g]     = ex2(0.2f*e0); g_Fi[r0g + 8] = ex2(0.2f*e1);
        g_Ej[r0g]     = ex2(f0);      g_Ej[r0g + 8] = ex2(f1);
        g_Fj[r0g]     = ex2(0.2f*f0); g_Fj[r0g + 8] = ex2(0.2f*f1);
    }

#pragma unroll
    for (int rr = 0; rr < 4; rr++) {
        const size_t row = row0 + w*4 + rr;
        const int4* arow = (const int4*)(adj + row*Nn);
#pragma unroll
        for (int c = 0; c < 8; c++) {
            const int4 v = __ldg(&arow[c*32 + lane]);
            unsigned nib = (unsigned)(v.x > 0) | ((unsigned)(v.y > 0) << 1)
                         | ((unsigned)(v.z > 0) << 2) | ((unsigned)(v.w > 0) << 3);
            nib <<= (lane & 7)*4;
            nib |= __shfl_xor_sync(0xffffffffu, nib, 1);
            nib |= __shfl_xor_sync(0xffffffffu, nib, 2);
            nib |= __shfl_xor_sync(0xffffffffu, nib, 4);
            if ((lane & 7) == 0)
                g_am[(size_t)(c*4 + (lane >> 3))*BN + row] = nib;
        }
    }
}

// ---------------------------------------------------------------------------
// Kernel 2: split-KV flash attention (partials), mma.sync tf32.
// Grid (16, Hh, Bx): blockIdx.x = (jhalf<<3) | i-tile. 128 thr = 4 warps,
// warp owns 32 i-rows. Each block covers 16 of 32 j-tiles; writes partial
// numerators (fp32) + denominators to g_pnum / g_pden.
// ---------------------------------------------------------------------------
__global__ void __launch_bounds__(128, 4) k_attn() {
    __shared__ float EjS[512], FjS[512];   // this half's Ej/Fj, permuted
    __shared__ float hsw[4][32*40];        // per-warp h tiles

    const int tid  = threadIdx.x;
    const int lane = tid & 31;
    const int w    = tid >> 5;
    const int qid  = lane >> 2;
    const int tq   = lane & 3;
    const int jh   = blockIdx.x >> 3;      // j-half 0/1
    const int i0   = (blockIdx.x & 7) * 128;
    const int hh   = blockIdx.y;
    const int b    = blockIdx.z;
    const int jt0  = jh * 16;
    const size_t bN = (size_t)b * Nn;

    // stage this half's Ej/Fj permuted: within 32-group, j=tq+4t -> pos=tq*8+t
    {
        const float* Ejsrc = g_Ej + (size_t)hh*BN + bN + jh*512;
        const float* Fjsrc = g_Fj + (size_t)hh*BN + bN + jh*512;
        for (int k = tid; k < 512; k += 128) {
            const int pos = (k & ~31) | (((k & 3) << 3) | ((k >> 2) & 7));
            EjS[pos] = Ejsrc[k];
            FjS[pos] = Fjsrc[k];
        }
    }

    float Eir[4], Fir[4], lden[4];
#pragma unroll
    for (int m = 0; m < 4; m++) {
        const size_t o = (size_t)hh*BN + bN + i0 + w*32 + qid + 8*m;
        Eir[m] = __ldg(&g_Ei[o]);
        Fir[m] = __ldg(&g_Fi[o]);
        lden[m] = 0.f;
    }

    float acc[2][4][4];
#pragma unroll
    for (int mt = 0; mt < 2; mt++)
#pragma unroll
        for (int nt = 0; nt < 4; nt++)
#pragma unroll
            for (int k = 0; k < 4; k++) acc[mt][nt][k] = 0.f;

    const float* htsrc = g_hT + (((size_t)b*Hh + hh) << 15);
    const unsigned* amp = g_am + bN + i0 + w*32 + qid;
    float* hw = hsw[w];
    __syncthreads();   // EjS/FjS visible

    for (int lt = 0; lt < 16; lt++) {
        const int jt = jt0 + lt;
        unsigned mb[4];
#pragma unroll
        for (int m = 0; m < 4; m++)
            mb[m] = __ldg(amp + (size_t)jt*BN + 8*m) >> tq;

        // ---- phase A: P in A-fragment registers (no MUFU)
        float ejt[8], fjt[8];
        *(float4*)&ejt[0] = *(const float4*)&EjS[lt*32 + tq*8];
        *(float4*)&ejt[4] = *(const float4*)&EjS[lt*32 + tq*8 + 4];
        *(float4*)&fjt[0] = *(const float4*)&FjS[lt*32 + tq*8];
        *(float4*)&fjt[4] = *(const float4*)&FjS[lt*32 + tq*8 + 4];

        uint32_t pu[4][8];
#pragma unroll
        for (int m = 0; m < 4; m++) {
#pragma unroll
            for (int t = 0; t < 8; t++) {
                float p = fmaxf(Eir[m]*ejt[t], Fir[m]*fjt[t]);
                p = (mb[m] & (1u << (4*t))) ? p : 0.f;
                const uint32_t pb = __float_as_uint(p) & 0xffffe000u;  // tf32 trunc
                lden[m] += __uint_as_float(pb);                        // consistent
                pu[m][t] = pb;
            }
        }

        // ---- stage h tile (per-warp private, no block sync)
        {
            const float4* hp = (const float4*)(htsrc + (size_t)jt*1024);
#pragma unroll
            for (int it = 0; it < 8; it++) {
                float4 v = hp[it*32 + lane];
                *(float4*)&hw[(it*4 + (lane >> 3))*40 + (lane & 7)*4] = v;
            }
        }
        __syncwarp();

        // ---- phase B: 32 x m16n8k8 tf32 mma
#pragma unroll
        for (int ksi = 0; ksi < 4; ksi++) {
            const float* h0 = &hw[(ksi*8 + tq)*40 + qid];
            const float* h1 = h0 + 4*40;
#pragma unroll
            for (int nt = 0; nt < 4; nt++) {
                const uint32_t b0 = __float_as_uint(h0[nt*8]);
                const uint32_t b1 = __float_as_uint(h1[nt*8]);
#pragma unroll
                for (int mt = 0; mt < 2; mt++) {
                    MMA_TF32(acc[mt][nt][0], acc[mt][nt][1],
                             acc[mt][nt][2], acc[mt][nt][3],
                             pu[2*mt][2*ksi], pu[2*mt+1][2*ksi],
                             pu[2*mt][2*ksi+1], pu[2*mt+1][2*ksi+1],
                             b0, b1);
                }
            }
        }
        __syncwarp();   // WAR before next lt overwrites hw
    }

    // ---- store partial denominators + numerators
    const size_t pb = (((size_t)jh*Bx + b)*Hh + hh) << 10;   // row base
#pragma unroll
    for (int m = 0; m < 4; m++) {
        lden[m] += __shfl_xor_sync(0xffffffffu, lden[m], 1);
        lden[m] += __shfl_xor_sync(0xffffffffu, lden[m], 2);
    }
    if (tq == 0) {
#pragma unroll
        for (int m = 0; m < 4; m++)
            g_pden[pb + i0 + w*32 + qid + 8*m] = lden[m];
    }
#pragma unroll
    for (int mt = 0; mt < 2; mt++) {
#pragma unroll
        for (int half = 0; half < 2; half++) {
            const int grow = i0 + w*32 + mt*16 + qid + 8*half;
            float* prow = g_pnum + ((pb + grow) << 5) + tq*2;
#pragma unroll
            for (int nt = 0; nt < 4; nt++) {
                float2 v = { acc[mt][nt][half*2 + 0], acc[mt][nt][half*2 + 1] };
                *(float2*)(prow + nt*8) = v;
            }
        }
    }
}

// ---------------------------------------------------------------------------
// Kernel 3: combine the two j-halves and normalize.
// thread t -> (b,hh,row,dq): out = (num0+num1) / (den0+den1).
// ---------------------------------------------------------------------------
__global__ void __launch_bounds__(256) k_norm(float* __restrict__ out) {
    const int t = blockIdx.x*256 + threadIdx.x;   // 0 .. 524287
    const int dq  = t & 7;
    const int rid = t >> 3;                        // (b*Hh+hh)*1024 + row
    const float4 n0 = *(const float4*)(g_pnum + ((size_t)rid << 5) + dq*4);
    const float4 n1 = *(const float4*)(g_pnum + (((size_t)(rid + 65536)) << 5) + dq*4);
    const float rl = 1.f / (g_pden[rid] + g_pden[rid + 65536]);
    const int row = rid & 1023;
    const int bhh = rid >> 10;
    const int bb  = bhh >> 2, hh = bhh & 3;
    float4 o = { (n0.x + n1.x)*rl, (n0.y + n1.y)*rl,
                 (n0.z + n1.z)*rl, (n0.w + n1.w)*rl };
    *(float4*)&out[(((size_t)bb << 10) + row)*HD + hh*32 + dq*4] = o;
}

// ---------------------------------------------------------------------------
extern "C" void kernel_launch(void* const* d_in, const int* in_sizes, int n_in,
                              void* d_out, int out_size) {
    const float* x = nullptr; const int* adj = nullptr;
    const float* W = nullptr; const float* bias = nullptr; const float* a = nullptr;
    for (int i = 0; i < n_in; i++) {
        switch (in_sizes[i]) {
            case Bx*Nn*DINc: x    = (const float*)d_in[i]; break;
            case Bx*Nn*Nn:   adj  = (const int*)  d_in[i]; break;
            case DINc*HD:    W    = (const float*)d_in[i]; break;
            case HD:         bias = (const float*)d_in[i]; break;
            case 2*Dd:       a    = (const float*)d_in[i]; break;
        }
    }
    k_gemm<<<BN/32, 256>>>(x, W, bias, a, adj);
    k_attn<<<dim3(16, Hh, Bx), 128>>>();
    k_norm<<<2048, 256>>>((float*)d_out);
}